// round 13
// baseline (speedup 1.0000x reference)
#include <cuda_runtime.h>
#include <cstdint>
#include <math.h>

#define CTAS 16
#define NTHR 512
#define NW   16     // warps per CTA; CTAS*NW = 256 global warps, 1 elem/warp

// ---------------- dynamic smem layout ------------------------------------------
struct __align__(16) Smem {
    float wl2d [NW * 264];       // 16896 B  (mbA)
    float hid  [256];            //  1024 B  (mbA)
    float whh  [3 * NW * 256];   // 49152 B  (mbB)
    float wcmb [NW * 512];       // 32768 B  (mbC)
    float wih  [3 * NW * 256];   // 49152 B  (mbC)
    float enc  [20 * 256];       // 20480 B  (mbC)
    float h0[256];
    float comb[256];
    float hnew[256];
    float logit[32];
    float olog[32];
    unsigned long long mbA, mbB, mbC, mbH;
};

// ---------------- helpers ------------------------------------------------------
__device__ __forceinline__ float warp_sum(float v) {
#pragma unroll
    for (int o = 16; o; o >>= 1) v += __shfl_xor_sync(0xffffffffu, v, o);
    return v;
}
__device__ __forceinline__ float warp_max(float v) {
#pragma unroll
    for (int o = 16; o; o >>= 1) v = fmaxf(v, __shfl_xor_sync(0xffffffffu, v, o));
    return v;
}
__device__ __forceinline__ float dot4(float4 a, float4 b) {
    return a.x * b.x + a.y * b.y + a.z * b.z + a.w * b.w;
}
__device__ __forceinline__ uint32_t smem_u32(const void* p) {
    uint32_t a;
    asm("{.reg .u64 t; cvta.to.shared.u64 t,%1; cvt.u32.u64 %0,t;}" : "=r"(a) : "l"(p));
    return a;
}
__device__ __forceinline__ void st_cluster(uint32_t laddr, int rank, float v) {
    uint32_t ra;
    asm("mapa.shared::cluster.u32 %0,%1,%2;" : "=r"(ra) : "r"(laddr), "r"(rank));
    asm volatile("st.shared::cluster.f32 [%0],%1;" :: "r"(ra), "f"(v) : "memory");
}
__device__ __forceinline__ void csync() {
    asm volatile("barrier.cluster.arrive.aligned;" ::: "memory");
    asm volatile("barrier.cluster.wait.aligned;" ::: "memory");
}
__device__ __forceinline__ void mbar_init(void* p, unsigned cnt) {
    asm volatile("mbarrier.init.shared.b64 [%0],%1;" :: "r"(smem_u32(p)), "r"(cnt) : "memory");
}
__device__ __forceinline__ void mbar_expect(void* p, unsigned bytes) {
    asm volatile("mbarrier.arrive.expect_tx.shared.b64 _,[%0],%1;"
                 :: "r"(smem_u32(p)), "r"(bytes) : "memory");
}
__device__ __forceinline__ void bulk_g2s(void* dst, const void* src, unsigned bytes, void* mbar) {
    asm volatile("cp.async.bulk.shared::cta.global.mbarrier::complete_tx::bytes [%0],[%1],%2,[%3];"
                 :: "r"(smem_u32(dst)), "l"(src), "r"(bytes), "r"(smem_u32(mbar)) : "memory");
}
__device__ __forceinline__ void mbar_wait(void* p) {
    uint32_t la = smem_u32(p);
    asm volatile(
        "{\n\t.reg .pred P;\n"
        "W%=:\n\t"
        "mbarrier.try_wait.parity.shared.b64 P,[%0],0;\n\t"
        "@!P bra W%=;\n\t}"
        :: "r"(la) : "memory");
}
__device__ __forceinline__ void mbar_arrive_cta0(void* p) {
    uint32_t la = smem_u32(p), ra;
    asm("mapa.shared::cluster.u32 %0,%1,%2;" : "=r"(ra) : "r"(la), "r"(0));
    asm volatile("mbarrier.arrive.release.cluster.shared::cluster.b64 _,[%0];"
                 :: "r"(ra) : "memory");
}
__device__ __forceinline__ void mbar_wait_acq(void* p) {
    uint32_t la = smem_u32(p);
    asm volatile(
        "{\n\t.reg .pred P;\n"
        "W%=:\n\t"
        "mbarrier.try_wait.parity.acquire.cluster.shared::cta.b64 P,[%0],0;\n\t"
        "@!P bra W%=;\n\t}"
        :: "r"(la) : "memory");
}
__device__ __forceinline__ float fsig(float x) {
    return __fdividef(1.f, 1.f + __expf(-x));
}

// ---------------- fused decoder step -------------------------------------------
__global__ void __launch_bounds__(NTHR, 1)
decoder_k(const int* __restrict__ inp,
          const float* __restrict__ hidden,   // [256]
          const float* __restrict__ enc,      // [20,256]
          const int* __restrict__ cond,       // [2]
          const int* __restrict__ is_head,    // [1]
          const float* __restrict__ emb,      // [29,256]
          const float* __restrict__ w_l2d,    // [256,264]
          const float* __restrict__ b_l2d,
          const float* __restrict__ w_attn,   // [20,512]
          const float* __restrict__ b_attn,
          const float* __restrict__ w_comb,   // [256,512]
          const float* __restrict__ b_comb,
          const float* __restrict__ w_ih,     // [768,256]
          const float* __restrict__ w_hh,     // [768,256]
          const float* __restrict__ b_ih,
          const float* __restrict__ b_hh,
          const float* __restrict__ w_out,    // [29,256]
          const float* __restrict__ b_out,
          float* __restrict__ out)            // [305]
{
    extern __shared__ Smem sm[];

    const int tid  = threadIdx.x;
    const int lane = tid & 31;
    const int wrp  = tid >> 5;                // 0..15
    const int bx   = blockIdx.x;
    const int gw   = bx * NW + wrp;           // 0..255 (owned element)

    // ---- t=0: mbarrier init + priority-split bulk copies --------------------
    if (tid == 0) {
        mbar_init(&sm->mbA, 1);
        mbar_init(&sm->mbB, 1);
        mbar_init(&sm->mbC, 1);
        mbar_init(&sm->mbH, CTAS);
    }
    __syncthreads();
    if (tid == 0) {
        // group A: P1 inputs (17.9 KB, lands first)
        mbar_expect(&sm->mbA, 16896u + 1024u);
        bulk_g2s(sm->wl2d, w_l2d + (bx * NW) * 264, NW * 264 * 4u, &sm->mbA);
        bulk_g2s(sm->hid, hidden, 1024u, &sm->mbA);
        // group B: P2 inputs (48 KB, whh only)
        mbar_expect(&sm->mbB, 49152u);
#pragma unroll
        for (int g = 0; g < 3; g++)
            bulk_g2s(&sm->whh[g * NW * 256], w_hh + (g * 256 + bx * NW) * 256,
                     NW * 256 * 4u, &sm->mbB);
        // group C: P3/P4 inputs (102.4 KB)
        mbar_expect(&sm->mbC, 32768u + 49152u + 20480u);
        bulk_g2s(sm->wcmb, w_comb + (bx * NW) * 512, NW * 512 * 4u, &sm->mbC);
#pragma unroll
        for (int g = 0; g < 3; g++)
            bulk_g2s(&sm->wih[g * NW * 256], w_ih + (g * 256 + bx * NW) * 256,
                     NW * 256 * 4u, &sm->mbC);
        bulk_g2s(sm->enc, enc, 20480u, &sm->mbC);
    }

    // ---- small LDGs (overlap with bulk flight) ------------------------------
    const int head = __ldg(is_head);
    const int iv   = __ldg(inp);
    int c0i = __ldg(cond), c1i = __ldg(cond + 1);
    // embedded row (dependent chain; first consumed in P2 -> hidden)
    const float* erow = emb + iv * 256;
    float4 e0 = __ldg((const float4*)erow + lane);
    float4 e1 = __ldg((const float4*)erow + 32 + lane);
    float bh3[3], bi3[3];
#pragma unroll
    for (int g = 0; g < 3; g++) {
        bh3[g] = __ldg(b_hh + g * 256 + gw);
        bi3[g] = __ldg(b_ih + g * 256 + gw);
    }
    float bc = __ldg(b_comb + gw);
    float bl = __ldg(b_l2d + gw);
    // distributed attention row (warp gw<20 owns row gw)
    float4 wa[4]; float ba = 0.f;
    if (gw < 20) {
        const float* w = w_attn + gw * 512;
#pragma unroll
        for (int k = 0; k < 4; k++) wa[k] = __ldg((const float4*)w + k * 32 + lane);
        ba = __ldg(b_attn + gw);
    }

    mbar_wait(&sm->mbA);                                      // group A landed

    // ---- P1: h0 row gw (head path, operands in smem) ------------------------
    float4 hx0 = *((const float4*)sm->hid + lane);
    float4 hx1 = *((const float4*)sm->hid + 32 + lane);
    float  h_e = sm->hid[gw];

    float h0v = 0.f;
    if (head) {
        const float* wr = &sm->wl2d[wrp * 264];
        float s = dot4(*((const float4*)wr + lane), hx0) +
                  dot4(*((const float4*)(wr + 128) + lane), hx1);
        if (lane < 8) {
            float xv = (lane == c0i || lane == 4 + c1i) ? 1.f : 0.f;
            s += wr[256 + lane] * xv;
        }
        h0v = warp_sum(s) + bl;
        if (lane < 16) st_cluster(smem_u32(&sm->h0[gw]), lane, h0v);
    }
    csync();                                                  // ---- cs1 (h0)

    // ---- P2: gh rows (3/warp) + distributed attn logits ---------------------
    mbar_wait(&sm->mbB);                                      // whh landed
    float4 x0, x1;
    if (head) { x0 = *((const float4*)sm->h0 + lane); x1 = *((const float4*)sm->h0 + 32 + lane); }
    else      { x0 = hx0; x1 = hx1; }
    float ghv[3];
#pragma unroll
    for (int g = 0; g < 3; g++) {
        const float* w = &sm->whh[(g * NW + wrp) * 256];
        ghv[g] = warp_sum(dot4(*((const float4*)w + lane), x0) +
                          dot4(*((const float4*)w + 32 + lane), x1)) + bh3[g];
    }
    if (gw < 20) {
        float s = warp_sum(dot4(wa[0], e0) + dot4(wa[1], e1) +
                           dot4(wa[2], x0) + dot4(wa[3], x1)) + ba;
        if (lane < CTAS) st_cluster(smem_u32(&sm->logit[gw]), lane, s);
    }
    csync();                                                  // ---- cs2 (logits)

    // ---- P3: softmax (warp-redundant) + attn_applied + comb -----------------
    mbar_wait(&sm->mbC);
    {
        const float* wcr = &sm->wcmb[wrp * 512];
        float ce = dot4(*((const float4*)wcr + lane), e0) +
                   dot4(*((const float4*)wcr + 32 + lane), e1);
        float v = (lane < 20) ? sm->logit[lane] : -1e30f;
        float m = warp_max(v);
        float ex = (lane < 20) ? __expf(v - m) : 0.f;
        float sum = warp_sum(ex);
        float w = __fdividef(ex, sum);
        if (gw == 0 && lane < 20) out[285 + lane] = w;
        float4 a0 = {0.f,0.f,0.f,0.f}, a1 = {0.f,0.f,0.f,0.f};
#pragma unroll
        for (int l = 0; l < 20; l++) {
            float wl = __shfl_sync(0xffffffffu, w, l);
            float4 q0 = *((const float4*)(sm->enc + l * 256) + lane);
            float4 q1 = *((const float4*)(sm->enc + l * 256) + 32 + lane);
            a0.x += wl*q0.x; a0.y += wl*q0.y; a0.z += wl*q0.z; a0.w += wl*q0.w;
            a1.x += wl*q1.x; a1.y += wl*q1.y; a1.z += wl*q1.z; a1.w += wl*q1.w;
        }
        float sc = warp_sum(ce + dot4(*((const float4*)wcr + 64 + lane), a0) +
                                 dot4(*((const float4*)wcr + 96 + lane), a1));
        sc = fmaxf(sc + bc, 0.f);
        if (lane < 16) st_cluster(smem_u32(&sm->comb[gw]), lane, sc);
    }
    csync();                                                  // ---- cs3 (comb)

    // ---- P4: gi rows (3/warp) + fused GRU -----------------------------------
    {
        float4 c0 = *((const float4*)sm->comb + lane);
        float4 c1 = *((const float4*)sm->comb + 32 + lane);
        float gi[3];
#pragma unroll
        for (int g = 0; g < 3; g++) {
            const float* w = &sm->wih[(g * NW + wrp) * 256];
            gi[g] = warp_sum(dot4(*((const float4*)w + lane), c0) +
                             dot4(*((const float4*)w + 32 + lane), c1)) + bi3[g];
        }
        float h0o = head ? h0v : h_e;
        float r = fsig(gi[0] + ghv[0]);
        float z = fsig(gi[1] + ghv[1]);
        float n = 2.f * fsig(2.f * (gi[2] + r * ghv[2])) - 1.f;
        float h = (1.f - z) * n + z * h0o;
        if (lane == 0) {
            st_cluster(smem_u32(&sm->hnew[gw]), 0, h);        // to CTA0 only
            out[29 + gw] = h;
        }
    }
    __syncthreads();
    if (tid == 0) mbar_arrive_cta0(&sm->mbH);                 // light hnew signal
    if (bx != 0) return;                                      // CTAs 1-15 exit

    // prefetch P5 weights while waiting
    float4 wo[2][2]; float bo[2];
#pragma unroll
    for (int r = 0; r < 2; r++) {
        const int o = wrp + r * NW;
        if (o < 29) {
            const float* w = w_out + o * 256;
            wo[r][0] = __ldg((const float4*)w + lane);
            wo[r][1] = __ldg((const float4*)w + 32 + lane);
            bo[r] = __ldg(b_out + o);
        }
    }
    mbar_wait_acq(&sm->mbH);                                  // all hnew landed

    // ---- P5 (CTA0): output logits + log_softmax -----------------------------
    {
        float4 H0 = *((const float4*)sm->hnew + lane);
        float4 H1 = *((const float4*)sm->hnew + 32 + lane);
#pragma unroll
        for (int r = 0; r < 2; r++) {
            const int o = wrp + r * NW;
            if (o < 29) {
                float s = warp_sum(dot4(wo[r][0], H0) + dot4(wo[r][1], H1)) + bo[r];
                if (lane == 0) sm->olog[o] = s;
            }
        }
    }
    __syncthreads();
    if (wrp == 0) {
        float v = (lane < 29) ? sm->olog[lane] : -1e30f;
        float m = warp_max(v);
        float e = (lane < 29) ? __expf(v - m) : 0.f;
        float sum = warp_sum(e);
        float ls = __logf(sum);
        if (lane < 29) out[lane] = v - m - ls;
    }
}

// ---------------- launch --------------------------------------------------------
extern "C" void kernel_launch(void* const* d_in, const int* in_sizes, int n_in,
                              void* d_out, int out_size) {
    (void)in_sizes; (void)n_in; (void)out_size;
    cudaFuncSetAttribute(decoder_k, cudaFuncAttributeNonPortableClusterSizeAllowed, 1);
    cudaFuncSetAttribute(decoder_k, cudaFuncAttributeMaxDynamicSharedMemorySize,
                         (int)sizeof(Smem));

    cudaLaunchAttribute at[1];
    at[0].id = cudaLaunchAttributeClusterDimension;
    at[0].val.clusterDim = {CTAS, 1, 1};

    cudaLaunchConfig_t cfg = {};
    cfg.gridDim  = {CTAS, 1, 1};
    cfg.blockDim = {NTHR, 1, 1};
    cfg.dynamicSmemBytes = sizeof(Smem);
    cfg.attrs = at;
    cfg.numAttrs = 1;

    cudaLaunchKernelEx(&cfg, decoder_k,
                       (const int*)d_in[0],  (const float*)d_in[1], (const float*)d_in[2],
                       (const int*)d_in[3],  (const int*)d_in[4],   (const float*)d_in[5],
                       (const float*)d_in[6],(const float*)d_in[7], (const float*)d_in[8],
                       (const float*)d_in[9],(const float*)d_in[10],(const float*)d_in[11],
                       (const float*)d_in[12],(const float*)d_in[13],(const float*)d_in[14],
                       (const float*)d_in[15],(const float*)d_in[16],(const float*)d_in[17],
                       (float*)d_out);
}

// round 14
// speedup vs baseline: 1.5714x; 1.5714x over previous
#include <cuda_runtime.h>
#include <cstdint>
#include <math.h>

#define CTAS 16
#define NTHR 256
#define NW   8      // warps per CTA; CTAS*NW = 128 global warps, 2 elems/warp

// ---------------- dynamic smem layout ------------------------------------------
struct __align__(16) Smem {
    float wl2d [2 * NW * 264];   // 16896 B  (mbA)
    float hid  [256];            //  1024 B  (mbA)
    float whh  [6 * NW * 256];   // 49152 B  (mbB)
    float wcmb [2 * NW * 512];   // 32768 B  (mbC)
    float wih  [6 * NW * 256];   // 49152 B  (mbC)
    float enc  [20 * 256];       // 20480 B  (mbC)
    float h0[256];
    float comb[256];
    float hnew[256];
    float logit[32];
    float olog[32];
    unsigned long long mbA, mbB, mbC, mbH;
};

// ---------------- helpers ------------------------------------------------------
__device__ __forceinline__ float warp_sum(float v) {
#pragma unroll
    for (int o = 16; o; o >>= 1) v += __shfl_xor_sync(0xffffffffu, v, o);
    return v;
}
__device__ __forceinline__ float warp_max(float v) {
#pragma unroll
    for (int o = 16; o; o >>= 1) v = fmaxf(v, __shfl_xor_sync(0xffffffffu, v, o));
    return v;
}
__device__ __forceinline__ float dot4(float4 a, float4 b) {
    return a.x * b.x + a.y * b.y + a.z * b.z + a.w * b.w;
}
__device__ __forceinline__ uint32_t smem_u32(const void* p) {
    uint32_t a;
    asm("{.reg .u64 t; cvta.to.shared.u64 t,%1; cvt.u32.u64 %0,t;}" : "=r"(a) : "l"(p));
    return a;
}
__device__ __forceinline__ void st_cluster(uint32_t laddr, int rank, float v) {
    uint32_t ra;
    asm("mapa.shared::cluster.u32 %0,%1,%2;" : "=r"(ra) : "r"(laddr), "r"(rank));
    asm volatile("st.shared::cluster.f32 [%0],%1;" :: "r"(ra), "f"(v) : "memory");
}
__device__ __forceinline__ void csync() {
    asm volatile("barrier.cluster.arrive.aligned;" ::: "memory");
    asm volatile("barrier.cluster.wait.aligned;" ::: "memory");
}
__device__ __forceinline__ void mbar_init(void* p, unsigned cnt) {
    asm volatile("mbarrier.init.shared.b64 [%0],%1;" :: "r"(smem_u32(p)), "r"(cnt) : "memory");
}
__device__ __forceinline__ void mbar_expect(void* p, unsigned bytes) {
    asm volatile("mbarrier.arrive.expect_tx.shared.b64 _,[%0],%1;"
                 :: "r"(smem_u32(p)), "r"(bytes) : "memory");
}
__device__ __forceinline__ void bulk_g2s(void* dst, const void* src, unsigned bytes, void* mbar) {
    asm volatile("cp.async.bulk.shared::cta.global.mbarrier::complete_tx::bytes [%0],[%1],%2,[%3];"
                 :: "r"(smem_u32(dst)), "l"(src), "r"(bytes), "r"(smem_u32(mbar)) : "memory");
}
__device__ __forceinline__ void mbar_wait(void* p) {
    uint32_t la = smem_u32(p);
    asm volatile(
        "{\n\t.reg .pred P;\n"
        "W%=:\n\t"
        "mbarrier.try_wait.parity.shared.b64 P,[%0],0;\n\t"
        "@!P bra W%=;\n\t}"
        :: "r"(la) : "memory");
}
__device__ __forceinline__ void mbar_arrive_cta0(void* p) {
    uint32_t la = smem_u32(p), ra;
    asm("mapa.shared::cluster.u32 %0,%1,%2;" : "=r"(ra) : "r"(la), "r"(0));
    asm volatile("mbarrier.arrive.release.cluster.shared::cluster.b64 _,[%0];"
                 :: "r"(ra) : "memory");
}
__device__ __forceinline__ void mbar_wait_acq(void* p) {
    uint32_t la = smem_u32(p);
    asm volatile(
        "{\n\t.reg .pred P;\n"
        "W%=:\n\t"
        "mbarrier.try_wait.parity.acquire.cluster.shared::cta.b64 P,[%0],0;\n\t"
        "@!P bra W%=;\n\t}"
        :: "r"(la) : "memory");
}
__device__ __forceinline__ float fsig(float x) {
    return __fdividef(1.f, 1.f + __expf(-x));
}

// ---------------- fused decoder step -------------------------------------------
__global__ void __launch_bounds__(NTHR, 1)
decoder_k(const int* __restrict__ inp,
          const float* __restrict__ hidden,   // [256]
          const float* __restrict__ enc,      // [20,256]
          const int* __restrict__ cond,       // [2]
          const int* __restrict__ is_head,    // [1]
          const float* __restrict__ emb,      // [29,256]
          const float* __restrict__ w_l2d,    // [256,264]
          const float* __restrict__ b_l2d,
          const float* __restrict__ w_attn,   // [20,512]
          const float* __restrict__ b_attn,
          const float* __restrict__ w_comb,   // [256,512]
          const float* __restrict__ b_comb,
          const float* __restrict__ w_ih,     // [768,256]
          const float* __restrict__ w_hh,     // [768,256]
          const float* __restrict__ b_ih,
          const float* __restrict__ b_hh,
          const float* __restrict__ w_out,    // [29,256]
          const float* __restrict__ b_out,
          float* __restrict__ out)            // [305]
{
    extern __shared__ Smem sm[];

    const int tid  = threadIdx.x;
    const int lane = tid & 31;
    const int wrp  = tid >> 5;                // 0..7
    const int bx   = blockIdx.x;
    const int gw   = bx * NW + wrp;           // 0..127
    const int e0i  = gw, e1i = gw + 128;

    // ---- t=0: mbarrier init + priority-split bulk copies --------------------
    if (tid == 0) {
        mbar_init(&sm->mbA, 1);
        mbar_init(&sm->mbB, 1);
        mbar_init(&sm->mbC, 1);
        mbar_init(&sm->mbH, CTAS);
    }
    __syncthreads();
    if (tid == 0) {
        // group A: P1 inputs (17.9 KB, lands first)
        mbar_expect(&sm->mbA, 16896u + 1024u);
#pragma unroll
        for (int e = 0; e < 2; e++)
            bulk_g2s(&sm->wl2d[e * NW * 264], w_l2d + (e * 128 + bx * NW) * 264,
                     NW * 264 * 4u, &sm->mbA);
        bulk_g2s(sm->hid, hidden, 1024u, &sm->mbA);
        // group B: P2 inputs (48 KB, whh only)
        mbar_expect(&sm->mbB, 49152u);
#pragma unroll
        for (int c = 0; c < 6; c++) {         // c = g*2+e
            int g = c >> 1, e = c & 1;
            bulk_g2s(&sm->whh[c * NW * 256], w_hh + (g * 256 + e * 128 + bx * NW) * 256,
                     NW * 256 * 4u, &sm->mbB);
        }
        // group C: P3/P4 inputs (102.4 KB)
        mbar_expect(&sm->mbC, 32768u + 49152u + 20480u);
#pragma unroll
        for (int e = 0; e < 2; e++)
            bulk_g2s(&sm->wcmb[e * NW * 512], w_comb + (e * 128 + bx * NW) * 512,
                     NW * 512 * 4u, &sm->mbC);
#pragma unroll
        for (int c = 0; c < 6; c++) {
            int g = c >> 1, e = c & 1;
            bulk_g2s(&sm->wih[c * NW * 256], w_ih + (g * 256 + e * 128 + bx * NW) * 256,
                     NW * 256 * 4u, &sm->mbC);
        }
        bulk_g2s(sm->enc, enc, 20480u, &sm->mbC);
    }

    // ---- small LDGs (overlap with bulk flight) ------------------------------
    const int head = __ldg(is_head);
    const int iv   = __ldg(inp);
    int c0i = __ldg(cond), c1i = __ldg(cond + 1);
    // embedded row (dependent chain; first consumed in P2 -> hidden by P1+cs1)
    const float* erow = emb + iv * 256;
    float4 e0 = __ldg((const float4*)erow + lane);
    float4 e1 = __ldg((const float4*)erow + 32 + lane);
    float bh6[6], bi6[6];
#pragma unroll
    for (int r = 0; r < 6; r++) {
        const int o = (r % 3) * 256 + (r < 3 ? e0i : e1i);
        bh6[r] = __ldg(b_hh + o);
        bi6[r] = __ldg(b_ih + o);
    }
    float bc0 = __ldg(b_comb + e0i), bc1 = __ldg(b_comb + e1i);
    float bl0 = __ldg(b_l2d + e0i),  bl1 = __ldg(b_l2d + e1i);
    // distributed attention row (warp gw<20 owns row gw)
    float4 wa[4]; float ba = 0.f;
    if (gw < 20) {
        const float* w = w_attn + gw * 512;
#pragma unroll
        for (int k = 0; k < 4; k++) wa[k] = __ldg((const float4*)w + k * 32 + lane);
        ba = __ldg(b_attn + gw);
    }

    mbar_wait(&sm->mbA);                                      // group A landed

    // ---- P1: h0 rows (head path, operands in smem) --------------------------
    float4 hx0 = *((const float4*)sm->hid + lane);
    float4 hx1 = *((const float4*)sm->hid + 32 + lane);
    float  h_e0 = sm->hid[e0i], h_e1 = sm->hid[e1i];

    float h00 = 0.f, h01 = 0.f;
    if (head) {
#pragma unroll
        for (int e = 0; e < 2; e++) {
            const float* wr = &sm->wl2d[(e * NW + wrp) * 264];
            float s = dot4(*((const float4*)wr + lane), hx0) +
                      dot4(*((const float4*)(wr + 128) + lane), hx1);
            if (lane < 8) {
                float xv = (lane == c0i || lane == 4 + c1i) ? 1.f : 0.f;
                s += wr[256 + lane] * xv;
            }
            s = warp_sum(s) + (e ? bl1 : bl0);
            if (e) h01 = s; else h00 = s;
        }
        if (lane < 16) st_cluster(smem_u32(&sm->h0[e0i]), lane, h00);
        else           st_cluster(smem_u32(&sm->h0[e1i]), lane - 16, h01);
    }
    csync();                                                  // ---- cs1 (h0)

    // ---- P2: gh + distributed attn logits -----------------------------------
    mbar_wait(&sm->mbB);                                      // whh landed
    float4 x0, x1;
    if (head) { x0 = *((const float4*)sm->h0 + lane); x1 = *((const float4*)sm->h0 + 32 + lane); }
    else      { x0 = hx0; x1 = hx1; }
    float ghv[6];
#pragma unroll
    for (int r = 0; r < 6; r++) {
        const int g = r % 3, e = r / 3;
        const float* w = &sm->whh[((g * 2 + e) * NW + wrp) * 256];
        ghv[r] = warp_sum(dot4(*((const float4*)w + lane), x0) +
                          dot4(*((const float4*)w + 32 + lane), x1)) + bh6[r];
    }
    if (gw < 20) {
        float s = warp_sum(dot4(wa[0], e0) + dot4(wa[1], e1) +
                           dot4(wa[2], x0) + dot4(wa[3], x1)) + ba;
        if (lane < CTAS) st_cluster(smem_u32(&sm->logit[gw]), lane, s);
    }
    csync();                                                  // ---- cs2 (logits)

    // ---- P3: softmax + attn_applied + comb (wcmb+enc from mbC) --------------
    mbar_wait(&sm->mbC);
    {
        const float* wcr0 = &sm->wcmb[wrp * 512];
        const float* wcr1 = &sm->wcmb[(NW + wrp) * 512];
        float ce0 = dot4(*((const float4*)wcr0 + lane), e0) +
                    dot4(*((const float4*)wcr0 + 32 + lane), e1);
        float ce1 = dot4(*((const float4*)wcr1 + lane), e0) +
                    dot4(*((const float4*)wcr1 + 32 + lane), e1);
        float v = (lane < 20) ? sm->logit[lane] : -1e30f;
        float m = warp_max(v);
        float ex = (lane < 20) ? __expf(v - m) : 0.f;
        float sum = warp_sum(ex);
        float w = __fdividef(ex, sum);
        if (gw == 0 && lane < 20) out[285 + lane] = w;
        float4 a0 = {0.f,0.f,0.f,0.f}, a1 = {0.f,0.f,0.f,0.f};
#pragma unroll
        for (int l = 0; l < 20; l++) {
            float wl = __shfl_sync(0xffffffffu, w, l);
            float4 q0 = *((const float4*)(sm->enc + l * 256) + lane);
            float4 q1 = *((const float4*)(sm->enc + l * 256) + 32 + lane);
            a0.x += wl*q0.x; a0.y += wl*q0.y; a0.z += wl*q0.z; a0.w += wl*q0.w;
            a1.x += wl*q1.x; a1.y += wl*q1.y; a1.z += wl*q1.z; a1.w += wl*q1.w;
        }
        float sc0 = warp_sum(ce0 + dot4(*((const float4*)wcr0 + 64 + lane), a0) +
                                   dot4(*((const float4*)wcr0 + 96 + lane), a1));
        float sc1 = warp_sum(ce1 + dot4(*((const float4*)wcr1 + 64 + lane), a0) +
                                   dot4(*((const float4*)wcr1 + 96 + lane), a1));
        sc0 = fmaxf(sc0 + bc0, 0.f);
        sc1 = fmaxf(sc1 + bc1, 0.f);
        if (lane < 16) st_cluster(smem_u32(&sm->comb[e0i]), lane, sc0);
        else           st_cluster(smem_u32(&sm->comb[e1i]), lane - 16, sc1);
    }
    csync();                                                  // ---- cs3 (comb)

    // ---- P4: gi + fused GRU --------------------------------------------------
    {
        float4 c0 = *((const float4*)sm->comb + lane);
        float4 c1 = *((const float4*)sm->comb + 32 + lane);
        float gi[6];
#pragma unroll
        for (int r = 0; r < 6; r++) {
            const int g = r % 3, e = r / 3;
            const float* w = &sm->wih[((g * 2 + e) * NW + wrp) * 256];
            gi[r] = warp_sum(dot4(*((const float4*)w + lane), c0) +
                             dot4(*((const float4*)w + 32 + lane), c1)) + bi6[r];
        }
#pragma unroll
        for (int e = 0; e < 2; e++) {
            const int o = e ? e1i : e0i;
            float h0o = head ? (e ? h01 : h00) : (e ? h_e1 : h_e0);
            float r = fsig(gi[e * 3 + 0] + ghv[e * 3 + 0]);
            float z = fsig(gi[e * 3 + 1] + ghv[e * 3 + 1]);
            float n = 2.f * fsig(2.f * (gi[e * 3 + 2] + r * ghv[e * 3 + 2])) - 1.f;
            float h = (1.f - z) * n + z * h0o;
            if (lane == 0) {
                st_cluster(smem_u32(&sm->hnew[o]), 0, h);     // to CTA0 only
                out[29 + o] = h;
            }
        }
    }
    __syncthreads();
    if (tid == 0) mbar_arrive_cta0(&sm->mbH);                 // light hnew signal
    if (bx != 0) return;                                      // CTAs 1-15 exit

    // prefetch P5 weights while waiting
    float4 wo[4][2]; float bo[4];
#pragma unroll
    for (int r = 0; r < 4; r++) {
        const int o = wrp + r * NW;
        if (o < 29) {
            const float* w = w_out + o * 256;
            wo[r][0] = __ldg((const float4*)w + lane);
            wo[r][1] = __ldg((const float4*)w + 32 + lane);
            bo[r] = __ldg(b_out + o);
        }
    }
    mbar_wait_acq(&sm->mbH);                                  // all hnew landed

    // ---- P5 (CTA0): output logits + log_softmax -----------------------------
    {
        float4 H0 = *((const float4*)sm->hnew + lane);
        float4 H1 = *((const float4*)sm->hnew + 32 + lane);
#pragma unroll
        for (int r = 0; r < 4; r++) {
            const int o = wrp + r * NW;
            if (o < 29) {
                float s = warp_sum(dot4(wo[r][0], H0) + dot4(wo[r][1], H1)) + bo[r];
                if (lane == 0) sm->olog[o] = s;
            }
        }
    }
    __syncthreads();
    if (wrp == 0) {
        float v = (lane < 29) ? sm->olog[lane] : -1e30f;
        float m = warp_max(v);
        float e = (lane < 29) ? __expf(v - m) : 0.f;
        float sum = warp_sum(e);
        float ls = __logf(sum);
        if (lane < 29) out[lane] = v - m - ls;
    }
}

// ---------------- launch --------------------------------------------------------
extern "C" void kernel_launch(void* const* d_in, const int* in_sizes, int n_in,
                              void* d_out, int out_size) {
    (void)in_sizes; (void)n_in; (void)out_size;
    cudaFuncSetAttribute(decoder_k, cudaFuncAttributeNonPortableClusterSizeAllowed, 1);
    cudaFuncSetAttribute(decoder_k, cudaFuncAttributeMaxDynamicSharedMemorySize,
                         (int)sizeof(Smem));

    cudaLaunchAttribute at[1];
    at[0].id = cudaLaunchAttributeClusterDimension;
    at[0].val.clusterDim = {CTAS, 1, 1};

    cudaLaunchConfig_t cfg = {};
    cfg.gridDim  = {CTAS, 1, 1};
    cfg.blockDim = {NTHR, 1, 1};
    cfg.dynamicSmemBytes = sizeof(Smem);
    cfg.attrs = at;
    cfg.numAttrs = 1;

    cudaLaunchKernelEx(&cfg, decoder_k,
                       (const int*)d_in[0],  (const float*)d_in[1], (const float*)d_in[2],
                       (const int*)d_in[3],  (const int*)d_in[4],   (const float*)d_in[5],
                       (const float*)d_in[6],(const float*)d_in[7], (const float*)d_in[8],
                       (const float*)d_in[9],(const float*)d_in[10],(const float*)d_in[11],
                       (const float*)d_in[12],(const float*)d_in[13],(const float*)d_in[14],
                       (const float*)d_in[15],(const float*)d_in[16],(const float*)d_in[17],
                       (float*)d_out);
}

// round 15
// speedup vs baseline: 1.5761x; 1.0030x over previous
#include <cuda_runtime.h>
#include <cstdint>
#include <math.h>

#define CTAS 16
#define NTHR 256
#define NW   8      // warps per CTA; CTAS*NW = 128 global warps, 2 elems/warp

// ---------------- dynamic smem layout ------------------------------------------
struct __align__(16) Smem {
    float wl2d [2 * NW * 264];   // 16896 B  (mbA)
    float hid  [256];            //  1024 B  (mbA)
    float whh  [6 * NW * 256];   // 49152 B  (mbB)
    float wcmb [2 * NW * 512];   // 32768 B  (mbC)
    float enc  [20 * 256];       // 20480 B  (mbC)
    float wih  [6 * NW * 256];   // 49152 B  (mbD)
    float h0[256];
    float comb[256];
    float hnew[256];
    float logit[32];
    float olog[32];
    unsigned long long mbA, mbB, mbC, mbD, mbH;
};

// ---------------- helpers ------------------------------------------------------
__device__ __forceinline__ float warp_sum(float v) {
#pragma unroll
    for (int o = 16; o; o >>= 1) v += __shfl_xor_sync(0xffffffffu, v, o);
    return v;
}
__device__ __forceinline__ float warp_max(float v) {
#pragma unroll
    for (int o = 16; o; o >>= 1) v = fmaxf(v, __shfl_xor_sync(0xffffffffu, v, o));
    return v;
}
__device__ __forceinline__ float dot4(float4 a, float4 b) {
    return a.x * b.x + a.y * b.y + a.z * b.z + a.w * b.w;
}
__device__ __forceinline__ uint32_t smem_u32(const void* p) {
    uint32_t a;
    asm("{.reg .u64 t; cvta.to.shared.u64 t,%1; cvt.u32.u64 %0,t;}" : "=r"(a) : "l"(p));
    return a;
}
__device__ __forceinline__ void st_cluster(uint32_t laddr, int rank, float v) {
    uint32_t ra;
    asm("mapa.shared::cluster.u32 %0,%1,%2;" : "=r"(ra) : "r"(laddr), "r"(rank));
    asm volatile("st.shared::cluster.f32 [%0],%1;" :: "r"(ra), "f"(v) : "memory");
}
__device__ __forceinline__ void carrive() {
    asm volatile("barrier.cluster.arrive.aligned;" ::: "memory");
}
__device__ __forceinline__ void cwait() {
    asm volatile("barrier.cluster.wait.aligned;" ::: "memory");
}
__device__ __forceinline__ void mbar_init(void* p, unsigned cnt) {
    asm volatile("mbarrier.init.shared.b64 [%0],%1;" :: "r"(smem_u32(p)), "r"(cnt) : "memory");
}
__device__ __forceinline__ void mbar_expect(void* p, unsigned bytes) {
    asm volatile("mbarrier.arrive.expect_tx.shared.b64 _,[%0],%1;"
                 :: "r"(smem_u32(p)), "r"(bytes) : "memory");
}
__device__ __forceinline__ void bulk_g2s(void* dst, const void* src, unsigned bytes, void* mbar) {
    asm volatile("cp.async.bulk.shared::cta.global.mbarrier::complete_tx::bytes [%0],[%1],%2,[%3];"
                 :: "r"(smem_u32(dst)), "l"(src), "r"(bytes), "r"(smem_u32(mbar)) : "memory");
}
__device__ __forceinline__ void mbar_wait(void* p) {
    uint32_t la = smem_u32(p);
    asm volatile(
        "{\n\t.reg .pred P;\n"
        "W%=:\n\t"
        "mbarrier.try_wait.parity.shared.b64 P,[%0],0;\n\t"
        "@!P bra W%=;\n\t}"
        :: "r"(la) : "memory");
}
__device__ __forceinline__ void mbar_arrive_cta0(void* p) {
    uint32_t la = smem_u32(p), ra;
    asm("mapa.shared::cluster.u32 %0,%1,%2;" : "=r"(ra) : "r"(la), "r"(0));
    asm volatile("mbarrier.arrive.release.cluster.shared::cluster.b64 _,[%0];"
                 :: "r"(ra) : "memory");
}
__device__ __forceinline__ void mbar_wait_acq(void* p) {
    uint32_t la = smem_u32(p);
    asm volatile(
        "{\n\t.reg .pred P;\n"
        "W%=:\n\t"
        "mbarrier.try_wait.parity.acquire.cluster.shared::cta.b64 P,[%0],0;\n\t"
        "@!P bra W%=;\n\t}"
        :: "r"(la) : "memory");
}
__device__ __forceinline__ float fsig(float x) {
    return __fdividef(1.f, 1.f + __expf(-x));
}

// ---------------- fused decoder step -------------------------------------------
__global__ void __launch_bounds__(NTHR, 1)
decoder_k(const int* __restrict__ inp,
          const float* __restrict__ hidden,   // [256]
          const float* __restrict__ enc,      // [20,256]
          const int* __restrict__ cond,       // [2]
          const int* __restrict__ is_head,    // [1]
          const float* __restrict__ emb,      // [29,256]
          const float* __restrict__ w_l2d,    // [256,264]
          const float* __restrict__ b_l2d,
          const float* __restrict__ w_attn,   // [20,512]
          const float* __restrict__ b_attn,
          const float* __restrict__ w_comb,   // [256,512]
          const float* __restrict__ b_comb,
          const float* __restrict__ w_ih,     // [768,256]
          const float* __restrict__ w_hh,     // [768,256]
          const float* __restrict__ b_ih,
          const float* __restrict__ b_hh,
          const float* __restrict__ w_out,    // [29,256]
          const float* __restrict__ b_out,
          float* __restrict__ out)            // [305]
{
    extern __shared__ Smem sm[];

    const int tid  = threadIdx.x;
    const int lane = tid & 31;
    const int wrp  = tid >> 5;                // 0..7
    const int bx   = blockIdx.x;
    const int gw   = bx * NW + wrp;           // 0..127
    const int e0i  = gw, e1i = gw + 128;

    // ---- t=0: mbarrier init + priority-split bulk copies --------------------
    if (tid == 0) {
        mbar_init(&sm->mbA, 1);
        mbar_init(&sm->mbB, 1);
        mbar_init(&sm->mbC, 1);
        mbar_init(&sm->mbD, 1);
        mbar_init(&sm->mbH, CTAS);
    }
    __syncthreads();
    if (tid == 0) {
        // group A: P1 inputs (17.9 KB, lands first)
        mbar_expect(&sm->mbA, 16896u + 1024u);
#pragma unroll
        for (int e = 0; e < 2; e++)
            bulk_g2s(&sm->wl2d[e * NW * 264], w_l2d + (e * 128 + bx * NW) * 264,
                     NW * 264 * 4u, &sm->mbA);
        bulk_g2s(sm->hid, hidden, 1024u, &sm->mbA);
        // group B: gh weights (48 KB)
        mbar_expect(&sm->mbB, 49152u);
#pragma unroll
        for (int c = 0; c < 6; c++) {         // c = g*2+e
            int g = c >> 1, e = c & 1;
            bulk_g2s(&sm->whh[c * NW * 256], w_hh + (g * 256 + e * 128 + bx * NW) * 256,
                     NW * 256 * 4u, &sm->mbB);
        }
        // group C: P3 inputs (53.2 KB)
        mbar_expect(&sm->mbC, 32768u + 20480u);
#pragma unroll
        for (int e = 0; e < 2; e++)
            bulk_g2s(&sm->wcmb[e * NW * 512], w_comb + (e * 128 + bx * NW) * 512,
                     NW * 512 * 4u, &sm->mbC);
        bulk_g2s(sm->enc, enc, 20480u, &sm->mbC);
        // group D: P4 inputs (48 KB)
        mbar_expect(&sm->mbD, 49152u);
#pragma unroll
        for (int c = 0; c < 6; c++) {
            int g = c >> 1, e = c & 1;
            bulk_g2s(&sm->wih[c * NW * 256], w_ih + (g * 256 + e * 128 + bx * NW) * 256,
                     NW * 256 * 4u, &sm->mbD);
        }
    }

    // ---- small LDGs (overlap with bulk flight) ------------------------------
    const int head = __ldg(is_head);
    const int iv   = __ldg(inp);
    int c0i = __ldg(cond), c1i = __ldg(cond + 1);
    const float* erow = emb + iv * 256;
    float4 e0 = __ldg((const float4*)erow + lane);
    float4 e1 = __ldg((const float4*)erow + 32 + lane);
    float bh6[6], bi6[6];
#pragma unroll
    for (int r = 0; r < 6; r++) {
        const int o = (r % 3) * 256 + (r < 3 ? e0i : e1i);
        bh6[r] = __ldg(b_hh + o);
        bi6[r] = __ldg(b_ih + o);
    }
    float bc0 = __ldg(b_comb + e0i), bc1 = __ldg(b_comb + e1i);
    float bl0 = __ldg(b_l2d + e0i),  bl1 = __ldg(b_l2d + e1i);
    // distributed attention row (warp gw<20 owns row gw)
    float4 wa[4]; float ba = 0.f;
    if (gw < 20) {
        const float* w = w_attn + gw * 512;
#pragma unroll
        for (int k = 0; k < 4; k++) wa[k] = __ldg((const float4*)w + k * 32 + lane);
        ba = __ldg(b_attn + gw);
    }

    mbar_wait(&sm->mbA);                                      // group A landed

    // ---- P1: h0 rows (head path, operands in smem) --------------------------
    float4 hx0 = *((const float4*)sm->hid + lane);
    float4 hx1 = *((const float4*)sm->hid + 32 + lane);
    float  h_e0 = sm->hid[e0i], h_e1 = sm->hid[e1i];

    float h00 = 0.f, h01 = 0.f;
    if (head) {
#pragma unroll
        for (int e = 0; e < 2; e++) {
            const float* wr = &sm->wl2d[(e * NW + wrp) * 264];
            float s = dot4(*((const float4*)wr + lane), hx0) +
                      dot4(*((const float4*)(wr + 128) + lane), hx1);
            if (lane < 8) {
                float xv = (lane == c0i || lane == 4 + c1i) ? 1.f : 0.f;
                s += wr[256 + lane] * xv;
            }
            s = warp_sum(s) + (e ? bl1 : bl0);
            if (e) h01 = s; else h00 = s;
        }
        if (lane < 16) st_cluster(smem_u32(&sm->h0[e0i]), lane, h00);
        else           st_cluster(smem_u32(&sm->h0[e1i]), lane - 16, h01);
    }
    carrive();                                                // ---- cs1 arrive
    // overlap: emb-half of attention logit (local-only partial)
    float aep = 0.f;
    if (gw < 20) aep = dot4(wa[0], e0) + dot4(wa[1], e1);
    cwait();                                                  // ---- cs1 wait

    // ---- P2: distributed attn logits (no whh dependency) --------------------
    float4 x0, x1;
    if (head) { x0 = *((const float4*)sm->h0 + lane); x1 = *((const float4*)sm->h0 + 32 + lane); }
    else      { x0 = hx0; x1 = hx1; }
    if (gw < 20) {
        float s = warp_sum(aep + dot4(wa[2], x0) + dot4(wa[3], x1)) + ba;
        if (lane < CTAS) st_cluster(smem_u32(&sm->logit[gw]), lane, s);
    }
    carrive();                                                // ---- cs2 arrive
    // overlap: gh rows (local-use only) under the barrier wait
    mbar_wait(&sm->mbB);                                      // whh landed
    float ghv[6];
#pragma unroll
    for (int r = 0; r < 6; r++) {
        const int g = r % 3, e = r / 3;
        const float* w = &sm->whh[((g * 2 + e) * NW + wrp) * 256];
        ghv[r] = warp_sum(dot4(*((const float4*)w + lane), x0) +
                          dot4(*((const float4*)w + 32 + lane), x1)) + bh6[r];
    }
    cwait();                                                  // ---- cs2 wait

    // ---- P3: softmax + attn_applied + comb (wcmb+enc from mbC) --------------
    mbar_wait(&sm->mbC);
    {
        const float* wcr0 = &sm->wcmb[wrp * 512];
        const float* wcr1 = &sm->wcmb[(NW + wrp) * 512];
        float ce0 = dot4(*((const float4*)wcr0 + lane), e0) +
                    dot4(*((const float4*)wcr0 + 32 + lane), e1);
        float ce1 = dot4(*((const float4*)wcr1 + lane), e0) +
                    dot4(*((const float4*)wcr1 + 32 + lane), e1);
        float v = (lane < 20) ? sm->logit[lane] : -1e30f;
        float m = warp_max(v);
        float ex = (lane < 20) ? __expf(v - m) : 0.f;
        float sum = warp_sum(ex);
        float w = __fdividef(ex, sum);
        if (gw == 0 && lane < 20) out[285 + lane] = w;
        float4 a0 = {0.f,0.f,0.f,0.f}, a1 = {0.f,0.f,0.f,0.f};
#pragma unroll
        for (int l = 0; l < 20; l++) {
            float wl = __shfl_sync(0xffffffffu, w, l);
            float4 q0 = *((const float4*)(sm->enc + l * 256) + lane);
            float4 q1 = *((const float4*)(sm->enc + l * 256) + 32 + lane);
            a0.x += wl*q0.x; a0.y += wl*q0.y; a0.z += wl*q0.z; a0.w += wl*q0.w;
            a1.x += wl*q1.x; a1.y += wl*q1.y; a1.z += wl*q1.z; a1.w += wl*q1.w;
        }
        float sc0 = warp_sum(ce0 + dot4(*((const float4*)wcr0 + 64 + lane), a0) +
                                   dot4(*((const float4*)wcr0 + 96 + lane), a1));
        float sc1 = warp_sum(ce1 + dot4(*((const float4*)wcr1 + 64 + lane), a0) +
                                   dot4(*((const float4*)wcr1 + 96 + lane), a1));
        sc0 = fmaxf(sc0 + bc0, 0.f);
        sc1 = fmaxf(sc1 + bc1, 0.f);
        if (lane < 16) st_cluster(smem_u32(&sm->comb[e0i]), lane, sc0);
        else           st_cluster(smem_u32(&sm->comb[e1i]), lane - 16, sc1);
    }
    carrive();                                                // ---- cs3 arrive
    mbar_wait(&sm->mbD);                                      // wih landed (overlap)
    cwait();                                                  // ---- cs3 wait

    // ---- P4: gi + fused GRU --------------------------------------------------
    {
        float4 c0 = *((const float4*)sm->comb + lane);
        float4 c1 = *((const float4*)sm->comb + 32 + lane);
        float gi[6];
#pragma unroll
        for (int r = 0; r < 6; r++) {
            const int g = r % 3, e = r / 3;
            const float* w = &sm->wih[((g * 2 + e) * NW + wrp) * 256];
            gi[r] = warp_sum(dot4(*((const float4*)w + lane), c0) +
                             dot4(*((const float4*)w + 32 + lane), c1)) + bi6[r];
        }
#pragma unroll
        for (int e = 0; e < 2; e++) {
            const int o = e ? e1i : e0i;
            float h0o = head ? (e ? h01 : h00) : (e ? h_e1 : h_e0);
            float r = fsig(gi[e * 3 + 0] + ghv[e * 3 + 0]);
            float z = fsig(gi[e * 3 + 1] + ghv[e * 3 + 1]);
            float n = 2.f * fsig(2.f * (gi[e * 3 + 2] + r * ghv[e * 3 + 2])) - 1.f;
            float h = (1.f - z) * n + z * h0o;
            if (lane == 0) {
                st_cluster(smem_u32(&sm->hnew[o]), 0, h);     // to CTA0 only
                out[29 + o] = h;
            }
        }
    }
    __syncthreads();
    if (tid == 0) mbar_arrive_cta0(&sm->mbH);                 // light hnew signal
    if (bx != 0) return;                                      // CTAs 1-15 exit

    // prefetch P5 weights while waiting
    float4 wo[4][2]; float bo[4];
#pragma unroll
    for (int r = 0; r < 4; r++) {
        const int o = wrp + r * NW;
        if (o < 29) {
            const float* w = w_out + o * 256;
            wo[r][0] = __ldg((const float4*)w + lane);
            wo[r][1] = __ldg((const float4*)w + 32 + lane);
            bo[r] = __ldg(b_out + o);
        }
    }
    mbar_wait_acq(&sm->mbH);                                  // all hnew landed

    // ---- P5 (CTA0): output logits + log_softmax -----------------------------
    {
        float4 H0 = *((const float4*)sm->hnew + lane);
        float4 H1 = *((const float4*)sm->hnew + 32 + lane);
#pragma unroll
        for (int r = 0; r < 4; r++) {
            const int o = wrp + r * NW;
            if (o < 29) {
                float s = warp_sum(dot4(wo[r][0], H0) + dot4(wo[r][1], H1)) + bo[r];
                if (lane == 0) sm->olog[o] = s;
            }
        }
    }
    __syncthreads();
    if (wrp == 0) {
        float v = (lane < 29) ? sm->olog[lane] : -1e30f;
        float m = warp_max(v);
        float e = (lane < 29) ? __expf(v - m) : 0.f;
        float sum = warp_sum(e);
        float ls = __logf(sum);
        if (lane < 29) out[lane] = v - m - ls;
    }
}

// ---------------- launch --------------------------------------------------------
extern "C" void kernel_launch(void* const* d_in, const int* in_sizes, int n_in,
                              void* d_out, int out_size) {
    (void)in_sizes; (void)n_in; (void)out_size;
    cudaFuncSetAttribute(decoder_k, cudaFuncAttributeNonPortableClusterSizeAllowed, 1);
    cudaFuncSetAttribute(decoder_k, cudaFuncAttributeMaxDynamicSharedMemorySize,
                         (int)sizeof(Smem));

    cudaLaunchAttribute at[1];
    at[0].id = cudaLaunchAttributeClusterDimension;
    at[0].val.clusterDim = {CTAS, 1, 1};

    cudaLaunchConfig_t cfg = {};
    cfg.gridDim  = {CTAS, 1, 1};
    cfg.blockDim = {NTHR, 1, 1};
    cfg.dynamicSmemBytes = sizeof(Smem);
    cfg.attrs = at;
    cfg.numAttrs = 1;

    cudaLaunchKernelEx(&cfg, decoder_k,
                       (const int*)d_in[0],  (const float*)d_in[1], (const float*)d_in[2],
                       (const int*)d_in[3],  (const int*)d_in[4],   (const float*)d_in[5],
                       (const float*)d_in[6],(const float*)d_in[7], (const float*)d_in[8],
                       (const float*)d_in[9],(const float*)d_in[10],(const float*)d_in[11],
                       (const float*)d_in[12],(const float*)d_in[13],(const float*)d_in[14],
                       (const float*)d_in[15],(const float*)d_in[16],(const float*)d_in[17],
                       (float*)d_out);
}